// round 12
// baseline (speedup 1.0000x reference)
#include <cuda_runtime.h>
#include <cstdint>

#define EPS_F 1e-5f
#define BDIM 128
#define CDIM 32
#define NA 12
#define NB 12
#define PDIM 8192

#define TPB 256
#define TILE_P 256
#define FPAD 13           // feature row stride: coprime with 32 -> conflict-free gather
#define ASTR 260          // aggS row stride: verified phase-1 STS pattern (R9)
#define WSTR 33           // wS row stride

// ---------------------------------------------------------------------------
// tf32 helpers (base-target ISA, sm_80+; compiles under compute_103)
// ---------------------------------------------------------------------------
__device__ __forceinline__ uint32_t to_tf32(float x) {
    uint32_t r;
    asm("cvt.rna.tf32.f32 %0, %1;" : "=r"(r) : "f"(x));
    return r;
}
__device__ __forceinline__ void mma_tf32(float& d0, float& d1, float& d2, float& d3,
                                         uint32_t a0, uint32_t a1, uint32_t a2, uint32_t a3,
                                         uint32_t b0, uint32_t b1) {
    asm volatile(
        "mma.sync.aligned.m16n8k8.row.col.f32.tf32.tf32.f32 "
        "{%0,%1,%2,%3}, {%4,%5,%6,%7}, {%8,%9}, {%0,%1,%2,%3};"
        : "+f"(d0), "+f"(d1), "+f"(d2), "+f"(d3)
        : "r"(a0), "r"(a1), "r"(a2), "r"(a3), "r"(b0), "r"(b1));
}

// ---------------------------------------------------------------------------
// Fused kernel:
//   Phase 0: fold bn1+conv+bn2 -> wS[o][c], biasS; stage padded feats.
//   Phase A: each thread loads its 8 W fragment elements per (mt,kt) ONCE,
//            splits to tf32 hi/lo -> held in registers for whole kernel.
//   Phase 1: verified c-parallel gather (lane=c, stride-13, conflict-free)
//            -> aggS[c][pt] (stride 260, conflict-free STS.128).
//   Phase 2: per warp, 4 n-tiles of 8 points: load B frags from aggS,
//            split hi/lo, 24 mma.sync m16n8k8 tf32 per n-tile
//            (2 m-tiles x 4 k-tiles x 3 split terms), bias+relu, STG.64.
// grid=(32,128), block=256, ~41KB smem, 2 CTAs/SM.
// ---------------------------------------------------------------------------
__global__ __launch_bounds__(TPB, 2) void feynnet_kernel(
    const float* __restrict__ feat_a, const float* __restrict__ feat_b,
    const int* __restrict__ assign_a, const int* __restrict__ assign_b,
    const float* __restrict__ conv_w,
    const float* __restrict__ g1, const float* __restrict__ b1,
    const float* __restrict__ m1, const float* __restrict__ v1,
    const float* __restrict__ g2, const float* __restrict__ b2,
    const float* __restrict__ m2, const float* __restrict__ v2,
    float* __restrict__ out) {
    __shared__ float s1[CDIM], t1v[CDIM], s2[CDIM], t2v[CDIM];
    __shared__ float faP[CDIM * FPAD];       // 1.7 KB
    __shared__ float fbP[CDIM * FPAD];       // 1.7 KB
    __shared__ float wS[CDIM * WSTR];        // folded W [o][c], 4.2 KB
    __shared__ float biasS[CDIM];
    __shared__ float aggS[CDIM * ASTR];      // [c][pt], 33.3 KB

    const int t = threadIdx.x;
    const int lane = t & 31;
    const int wid = t >> 5;
    const int g = lane >> 2;       // groupID   (0..7)
    const int tg = lane & 3;       // threadID_in_group (0..3)
    const int b = blockIdx.y;
    const int ptile = blockIdx.x * TILE_P;

    // ---- Phase 0a: bn scales ----
    if (t < CDIM) {
        float sc1 = g1[t] * rsqrtf(v1[t] + EPS_F);
        s1[t] = sc1;
        t1v[t] = b1[t] - m1[t] * sc1;
        float sc2 = g2[t] * rsqrtf(v2[t] + EPS_F);
        s2[t] = sc2;
        t2v[t] = b2[t] - m2[t] * sc2;
    }
    __syncthreads();

    // ---- Phase 0b: folded W, bias, padded feats ----
    for (int i = t; i < CDIM * CDIM; i += TPB) {
        int o = i >> 5, c = i & 31;
        wS[o * WSTR + c] = conv_w[i] * s1[c] * s2[o];
    }
    if (t < CDIM) {
        float s = 0.f;
        #pragma unroll
        for (int c = 0; c < CDIM; c++) s += conv_w[t * CDIM + c] * t1v[c];
        biasS[t] = s * s2[t] + t2v[t];
    }
    for (int i = t; i < CDIM * NA; i += TPB) {       // 384 > TPB: strided
        int c = i / NA, j = i - c * NA;
        faP[c * FPAD + j] = feat_a[b * CDIM * NA + i];
    }
    for (int i = t; i < CDIM * NB; i += TPB) {
        int c = i / NB, j = i - c * NB;
        fbP[c * FPAD + j] = feat_b[b * CDIM * NB + i];
    }
    __syncthreads();

    // ---- Phase A: W fragments (tf32 hi/lo), resident in registers ----
    // mma m16n8k8 A-frag: a0=(row g, col tg) a1=(g+8,tg) a2=(g,tg+4) a3=(g+8,tg+4)
    uint32_t aH[2][4][4], aL[2][4][4];
    #pragma unroll
    for (int mt = 0; mt < 2; mt++) {
        #pragma unroll
        for (int kt = 0; kt < 4; kt++) {
            int r0 = (mt * 16 + g) * WSTR, r1 = (mt * 16 + g + 8) * WSTR;
            int c0 = kt * 8 + tg;
            float w0 = wS[r0 + c0];
            float w1 = wS[r1 + c0];
            float w2 = wS[r0 + c0 + 4];
            float w3 = wS[r1 + c0 + 4];
            aH[mt][kt][0] = to_tf32(w0);
            aH[mt][kt][1] = to_tf32(w1);
            aH[mt][kt][2] = to_tf32(w2);
            aH[mt][kt][3] = to_tf32(w3);
            aL[mt][kt][0] = to_tf32(w0 - __uint_as_float(aH[mt][kt][0]));
            aL[mt][kt][1] = to_tf32(w1 - __uint_as_float(aH[mt][kt][1]));
            aL[mt][kt][2] = to_tf32(w2 - __uint_as_float(aH[mt][kt][2]));
            aL[mt][kt][3] = to_tf32(w3 - __uint_as_float(aH[mt][kt][3]));
        }
    }
    float bias_r[2][2];
    bias_r[0][0] = biasS[g];
    bias_r[0][1] = biasS[g + 8];
    bias_r[1][0] = biasS[16 + g];
    bias_r[1][1] = biasS[24 + g];

    // ---- Phase 1: c-parallel gather + max (verified R9 pattern) ----
    {
        const int crow = lane * FPAD;        // lane = channel
        float* aggRow = aggS + lane * ASTR;
        #pragma unroll
        for (int step = 0; step < 8; step++) {
            const int p0 = wid * 32 + step * 4;
            const int4 qa0 = __ldg((const int4*)(assign_a + 2 * (ptile + p0)));
            const int4 qa1 = __ldg((const int4*)(assign_a + 2 * (ptile + p0) + 4));
            const int4 qb0 = __ldg((const int4*)(assign_b + 2 * (ptile + p0)));
            const int4 qb1 = __ldg((const int4*)(assign_b + 2 * (ptile + p0) + 4));

            float v0 = fmaxf(fmaxf(faP[crow + qa0.x], faP[crow + qa0.y]),
                             fmaxf(fbP[crow + qb0.x], fbP[crow + qb0.y]));
            float v1 = fmaxf(fmaxf(faP[crow + qa0.z], faP[crow + qa0.w]),
                             fmaxf(fbP[crow + qb0.z], fbP[crow + qb0.w]));
            float v2 = fmaxf(fmaxf(faP[crow + qa1.x], faP[crow + qa1.y]),
                             fmaxf(fbP[crow + qb1.x], fbP[crow + qb1.y]));
            float v3 = fmaxf(fmaxf(faP[crow + qa1.z], faP[crow + qa1.w]),
                             fmaxf(fbP[crow + qb1.z], fbP[crow + qb1.w]));

            *reinterpret_cast<float4*>(aggRow + p0) = make_float4(v0, v1, v2, v3);
        }
    }
    __syncthreads();

    // ---- Phase 2: mma over 4 n-tiles ----
    const int wpt0 = wid * 32;               // this warp's point base in tile
    #pragma unroll
    for (int nt = 0; nt < 4; nt++) {
        // B frag: b0 = agg[kt*8+tg][pt], b1 = agg[kt*8+tg+4][pt], pt = g
        const int ptb = wpt0 + nt * 8 + g;
        uint32_t bh[4][2], bl[4][2];
        #pragma unroll
        for (int kt = 0; kt < 4; kt++) {
            float f0 = aggS[(kt * 8 + tg) * ASTR + ptb];
            float f1 = aggS[(kt * 8 + tg + 4) * ASTR + ptb];
            bh[kt][0] = to_tf32(f0);
            bh[kt][1] = to_tf32(f1);
            bl[kt][0] = to_tf32(f0 - __uint_as_float(bh[kt][0]));
            bl[kt][1] = to_tf32(f1 - __uint_as_float(bh[kt][1]));
        }

        float d[2][4] = {{0.f, 0.f, 0.f, 0.f}, {0.f, 0.f, 0.f, 0.f}};
        #pragma unroll
        for (int kt = 0; kt < 4; kt++) {
            #pragma unroll
            for (int mt = 0; mt < 2; mt++) {
                mma_tf32(d[mt][0], d[mt][1], d[mt][2], d[mt][3],
                         aH[mt][kt][0], aH[mt][kt][1], aH[mt][kt][2], aH[mt][kt][3],
                         bh[kt][0], bh[kt][1]);
                mma_tf32(d[mt][0], d[mt][1], d[mt][2], d[mt][3],
                         aL[mt][kt][0], aL[mt][kt][1], aL[mt][kt][2], aL[mt][kt][3],
                         bh[kt][0], bh[kt][1]);
                mma_tf32(d[mt][0], d[mt][1], d[mt][2], d[mt][3],
                         aH[mt][kt][0], aH[mt][kt][1], aH[mt][kt][2], aH[mt][kt][3],
                         bl[kt][0], bl[kt][1]);
            }
        }

        // Epilogue: D rows o = mt*16+g (+8), cols pt = nt*8 + tg*2 (+1)
        const size_t pcol = (size_t)ptile + wpt0 + nt * 8 + tg * 2;
        float* ob = out + (size_t)b * CDIM * PDIM + pcol;
        #pragma unroll
        for (int mt = 0; mt < 2; mt++) {
            float x0 = fmaxf(d[mt][0] + bias_r[mt][0], 0.f);
            float x1 = fmaxf(d[mt][1] + bias_r[mt][0], 0.f);
            float x2 = fmaxf(d[mt][2] + bias_r[mt][1], 0.f);
            float x3 = fmaxf(d[mt][3] + bias_r[mt][1], 0.f);
            *reinterpret_cast<float2*>(ob + (size_t)(mt * 16 + g) * PDIM) =
                make_float2(x0, x1);
            *reinterpret_cast<float2*>(ob + (size_t)(mt * 16 + g + 8) * PDIM) =
                make_float2(x2, x3);
        }
    }
}

// ---------------------------------------------------------------------------
// Launch
// ---------------------------------------------------------------------------
extern "C" void kernel_launch(void* const* d_in, const int* in_sizes, int n_in,
                              void* d_out, int out_size) {
    const float* feat_a = (const float*)d_in[0];
    const float* feat_b = (const float*)d_in[1];
    const int* assign_a = (const int*)d_in[2];
    const int* assign_b = (const int*)d_in[3];
    const float* bn1_gamma = (const float*)d_in[4];
    const float* bn1_beta = (const float*)d_in[5];
    const float* bn1_mean = (const float*)d_in[6];
    const float* bn1_var = (const float*)d_in[7];
    const float* conv_w = (const float*)d_in[8];
    const float* bn2_gamma = (const float*)d_in[9];
    const float* bn2_beta = (const float*)d_in[10];
    const float* bn2_mean = (const float*)d_in[11];
    const float* bn2_var = (const float*)d_in[12];
    float* out = (float*)d_out;

    dim3 grid(PDIM / TILE_P, BDIM);
    feynnet_kernel<<<grid, TPB>>>(feat_a, feat_b, assign_a, assign_b,
                                  conv_w,
                                  bn1_gamma, bn1_beta, bn1_mean, bn1_var,
                                  bn2_gamma, bn2_beta, bn2_mean, bn2_var,
                                  out);
}

// round 13
// speedup vs baseline: 1.4507x; 1.4507x over previous
#include <cuda_runtime.h>
#include <cstdint>

#define EPS_F 1e-5f
#define BDIM 128
#define CDIM 32
#define NA 12
#define NB 12
#define PDIM 8192

#define TPB 256
#define TILE_P 1024        // per block; 4 chunks of 256
#define CHUNK 256
#define NCHUNK (TILE_P / CHUNK)
#define FPAD 13            // feature row stride (odd -> conflict-free gather)
#define ASTR 260           // aggS row stride (65 granules, odd -> conflict-free STS.128/LDS.128)
#define WSTR 36            // wT row stride (16B-aligned rows)

// ---------------------------------------------------------------------------
// Packed f32x2 helpers (sm_103a FFMA2 — ptxas never emits this from C++)
// ---------------------------------------------------------------------------
__device__ __forceinline__ unsigned long long pack2(float lo, float hi) {
    unsigned long long r;
    asm("mov.b64 %0, {%1, %2};" : "=l"(r) : "f"(lo), "f"(hi));
    return r;
}
__device__ __forceinline__ void unpack2(unsigned long long v, float& lo, float& hi) {
    asm("mov.b64 {%0, %1}, %2;" : "=f"(lo), "=f"(hi) : "l"(v));
}
__device__ __forceinline__ unsigned long long fma2(unsigned long long a,
                                                   unsigned long long b,
                                                   unsigned long long c) {
    unsigned long long d;
    asm("fma.rn.f32x2 %0, %1, %2, %3;" : "=l"(d) : "l"(a), "l"(b), "l"(c));
    return d;
}

// ---------------------------------------------------------------------------
// Fused kernel. Per block: setup once, then 4 chunk-iterations of
//   {prefetch idx -> sync -> shfl-driven gather into aggS -> sync -> GEMM}.
// Phase 1: lane = channel c (stride-13 rows, conflict-free LDS); point
//   indices arrive via __shfl from the prefetching thread (no LDG chain).
// Phase 2: warp pair = o-group of 8 (og = wid>>1, warp-uniform). Per c:
//   2 uniform LDS.128 from wT[c][o0] + 8 pack movs + 1 agg LDS.128
//   (4 pts/lane, phase-perfect) + 16 FFMA2. Thread tile 8o x 4pt.
// grid = (PDIM/TILE_P, BDIM) = (8,128); block = 256; ~41.6KB smem, 3 CTAs/SM.
// ---------------------------------------------------------------------------
__global__ __launch_bounds__(TPB, 3) void feynnet_kernel(
    const float* __restrict__ feat_a, const float* __restrict__ feat_b,
    const int* __restrict__ assign_a, const int* __restrict__ assign_b,
    const float* __restrict__ conv_w,
    const float* __restrict__ g1, const float* __restrict__ b1,
    const float* __restrict__ m1, const float* __restrict__ v1,
    const float* __restrict__ g2, const float* __restrict__ b2,
    const float* __restrict__ m2, const float* __restrict__ v2,
    float* __restrict__ out) {
    __shared__ float s1[CDIM], t1v[CDIM], s2[CDIM], t2v[CDIM];
    __shared__ float faP[CDIM * FPAD];      // 1.7 KB
    __shared__ float fbP[CDIM * FPAD];      // 1.7 KB
    __shared__ float wT[CDIM * WSTR];       // folded W, [c][o], 4.6 KB
    __shared__ float biasS[CDIM];
    __shared__ float aggS[CDIM * ASTR];     // [c][pt in chunk], 33.3 KB

    const int t = threadIdx.x;
    const int lane = t & 31;
    const int wid = t >> 5;
    const int b = blockIdx.y;
    const int ptile = blockIdx.x * TILE_P;

    // ---- Setup (once per block) ----
    if (t < CDIM) {
        float sc1 = g1[t] * rsqrtf(v1[t] + EPS_F);
        s1[t] = sc1;
        t1v[t] = b1[t] - m1[t] * sc1;
        float sc2 = g2[t] * rsqrtf(v2[t] + EPS_F);
        s2[t] = sc2;
        t2v[t] = b2[t] - m2[t] * sc2;
    }
    __syncthreads();
    for (int i = t; i < CDIM * CDIM; i += TPB) {
        int o = i >> 5, c = i & 31;
        wT[c * WSTR + o] = conv_w[i] * s1[c] * s2[o];   // [c][o]
    }
    if (t < CDIM) {
        float s = 0.f;
        #pragma unroll
        for (int c = 0; c < CDIM; c++) s += conv_w[t * CDIM + c] * t1v[c];
        biasS[t] = s * s2[t] + t2v[t];
    }
    for (int i = t; i < CDIM * NA; i += TPB) {          // 384 > TPB: strided
        int c = i / NA, j = i - c * NA;
        faP[c * FPAD + j] = feat_a[b * CDIM * NA + i];
    }
    for (int i = t; i < CDIM * NB; i += TPB) {
        int c = i / NB, j = i - c * NB;
        fbP[c * FPAD + j] = feat_b[b * CDIM * NB + i];
    }

    // Phase-2 thread mapping (constant across chunks)
    const int og = wid >> 1;                 // 0..3  -> o-group of 8 (warp-uniform)
    const int half = wid & 1;                // chunk half (pts 0-127 / 128-255)
    const int o0 = og * 8;
    const int p0 = half * 128 + 4 * lane;    // this thread's 4 points in chunk

    for (int ck = 0; ck < NCHUNK; ck++) {
        const int cbase = ptile + ck * CHUNK;

        // ---- Prefetch this chunk's indices (thread t owns point cbase+t) ----
        const int2 aa = __ldg((const int2*)(assign_a + 2 * (cbase + t)));
        const int2 ab = __ldg((const int2*)(assign_b + 2 * (cbase + t)));

        __syncthreads();   // aggS free (previous chunk's GEMM done) + setup done

        // ---- Phase 1: gather + max; warp w covers chunk pts [32w, 32w+32) ----
        {
            const int crow = lane * FPAD;    // lane = channel
            float* aggRow = aggS + lane * ASTR + wid * 32;
            #pragma unroll
            for (int j4 = 0; j4 < 8; j4++) {
                float v[4];
                #pragma unroll
                for (int k = 0; k < 4; k++) {
                    const int j = j4 * 4 + k;
                    const int ax = __shfl_sync(0xffffffffu, aa.x, j);
                    const int ay = __shfl_sync(0xffffffffu, aa.y, j);
                    const int bx = __shfl_sync(0xffffffffu, ab.x, j);
                    const int by = __shfl_sync(0xffffffffu, ab.y, j);
                    v[k] = fmaxf(fmaxf(faP[crow + ax], faP[crow + ay]),
                                 fmaxf(fbP[crow + bx], fbP[crow + by]));
                }
                *reinterpret_cast<float4*>(aggRow + j4 * 4) =
                    make_float4(v[0], v[1], v[2], v[3]);
            }
        }
        __syncthreads();

        // ---- Phase 2: thread tile 8 o x 4 pts ----
        unsigned long long acc[8][2];
        #pragma unroll
        for (int o = 0; o < 8; o++) {
            float bb = biasS[o0 + o];
            unsigned long long bp = pack2(bb, bb);
            acc[o][0] = bp;
            acc[o][1] = bp;
        }

        #pragma unroll
        for (int c = 0; c < CDIM; c++) {
            // 8 o-weights via 2 warp-uniform vector loads
            const float4 wa = *reinterpret_cast<const float4*>(wT + c * WSTR + o0);
            const float4 wb = *reinterpret_cast<const float4*>(wT + c * WSTR + o0 + 4);
            const ulonglong2 a =
                *reinterpret_cast<const ulonglong2*>(aggS + c * ASTR + p0);

            unsigned long long w;
            w = pack2(wa.x, wa.x);
            acc[0][0] = fma2(w, a.x, acc[0][0]);
            acc[0][1] = fma2(w, a.y, acc[0][1]);
            w = pack2(wa.y, wa.y);
            acc[1][0] = fma2(w, a.x, acc[1][0]);
            acc[1][1] = fma2(w, a.y, acc[1][1]);
            w = pack2(wa.z, wa.z);
            acc[2][0] = fma2(w, a.x, acc[2][0]);
            acc[2][1] = fma2(w, a.y, acc[2][1]);
            w = pack2(wa.w, wa.w);
            acc[3][0] = fma2(w, a.x, acc[3][0]);
            acc[3][1] = fma2(w, a.y, acc[3][1]);
            w = pack2(wb.x, wb.x);
            acc[4][0] = fma2(w, a.x, acc[4][0]);
            acc[4][1] = fma2(w, a.y, acc[4][1]);
            w = pack2(wb.y, wb.y);
            acc[5][0] = fma2(w, a.x, acc[5][0]);
            acc[5][1] = fma2(w, a.y, acc[5][1]);
            w = pack2(wb.z, wb.z);
            acc[6][0] = fma2(w, a.x, acc[6][0]);
            acc[6][1] = fma2(w, a.y, acc[6][1]);
            w = pack2(wb.w, wb.w);
            acc[7][0] = fma2(w, a.x, acc[7][0]);
            acc[7][1] = fma2(w, a.y, acc[7][1]);
        }

        // ---- Epilogue: relu + coalesced float4 stores ----
        float* ob = out + (size_t)b * CDIM * PDIM + cbase + p0;
        #pragma unroll
        for (int o = 0; o < 8; o++) {
            float x0, x1, x2, x3;
            unpack2(acc[o][0], x0, x1);
            unpack2(acc[o][1], x2, x3);
            *reinterpret_cast<float4*>(ob + (size_t)(o0 + o) * PDIM) =
                make_float4(fmaxf(x0, 0.f), fmaxf(x1, 0.f),
                            fmaxf(x2, 0.f), fmaxf(x3, 0.f));
        }
    }
}

// ---------------------------------------------------------------------------
// Launch
// ---------------------------------------------------------------------------
extern "C" void kernel_launch(void* const* d_in, const int* in_sizes, int n_in,
                              void* d_out, int out_size) {
    const float* feat_a = (const float*)d_in[0];
    const float* feat_b = (const float*)d_in[1];
    const int* assign_a = (const int*)d_in[2];
    const int* assign_b = (const int*)d_in[3];
    const float* bn1_gamma = (const float*)d_in[4];
    const float* bn1_beta = (const float*)d_in[5];
    const float* bn1_mean = (const float*)d_in[6];
    const float* bn1_var = (const float*)d_in[7];
    const float* conv_w = (const float*)d_in[8];
    const float* bn2_gamma = (const float*)d_in[9];
    const float* bn2_beta = (const float*)d_in[10];
    const float* bn2_mean = (const float*)d_in[11];
    const float* bn2_var = (const float*)d_in[12];
    float* out = (float*)d_out;

    dim3 grid(PDIM / TILE_P, BDIM);
    feynnet_kernel<<<grid, TPB>>>(feat_a, feat_b, assign_a, assign_b,
                                  conv_w,
                                  bn1_gamma, bn1_beta, bn1_mean, bn1_var,
                                  bn2_gamma, bn2_beta, bn2_mean, bn2_var,
                                  out);
}